// round 1
// baseline (speedup 1.0000x reference)
#include <cuda_runtime.h>
#include <math.h>

#define BATCH 2
#define NP    4096
#define HH    128
#define WW    128
#define KK    8
#define RAD   0.05f
#define RAD2  (RAD * RAD)
#define TILE  16
#define TX    (WW / TILE)   // 8
#define TYN   (HH / TILE)   // 8
#define NTILES (TX * TYN)   // 64

#define ZINF 3.0e38f

// Scratch (no cudaMalloc allowed)
__device__ float g_px[BATCH * NP];
__device__ float g_py[BATCH * NP];
__device__ float g_pz[BATCH * NP];
__device__ int   g_cnt[BATCH * NTILES];
__device__ int   g_list[BATCH * NTILES * NP];

// ---------------------------------------------------------------------------
// Kernel 0: zero the per-tile counters (graph replays require re-zeroing)
// ---------------------------------------------------------------------------
__global__ void zero_counts_kernel() {
    int t = blockIdx.x * blockDim.x + threadIdx.x;
    if (t < BATCH * NTILES) g_cnt[t] = 0;
}

// ---------------------------------------------------------------------------
// Kernel 1: world->view->NDC transform + scatter point into overlapped tiles
// ---------------------------------------------------------------------------
__global__ void transform_bin_kernel(const float* __restrict__ pts,
                                     const float* __restrict__ Rm,
                                     const float* __restrict__ Tv,
                                     const float* __restrict__ Fc) {
    int t = blockIdx.x * blockDim.x + threadIdx.x;
    if (t >= BATCH * NP) return;
    int b = t / NP;
    int p = t - b * NP;

    float p0 = pts[t * 3 + 0];
    float p1 = pts[t * 3 + 1];
    float p2 = pts[t * 3 + 2];
    const float* Rb = Rm + b * 9;
    const float* Tb = Tv + b * 3;

    // row-vector convention: v[j] = sum_i p[i] * R[i][j] + T[j]
    float xv = p0 * Rb[0] + p1 * Rb[3] + p2 * Rb[6] + Tb[0];
    float yv = p0 * Rb[1] + p1 * Rb[4] + p2 * Rb[7] + Tb[1];
    float zv = p0 * Rb[2] + p1 * Rb[5] + p2 * Rb[8] + Tb[2];

    float f = Fc[b];
    float x = f * xv / zv;   // IEEE div, matches (focal * x) / z
    float y = f * yv / zv;

    g_px[t] = x;
    g_py[t] = y;
    g_pz[t] = zv;

    if (!(zv > 0.0f)) return;

    // pixel ix covered iff |gx(ix) - x| < r, gx(ix) = 1 - (ix+0.5)/64
    // => ix in ( 64*(1-x-r)-0.5 , 64*(1-x+r)-0.5 )   (conservative bounds)
    float lox = 64.0f * (1.0f - x - RAD) - 0.5f;
    float hix = 64.0f * (1.0f - x + RAD) - 0.5f;
    float loy = 64.0f * (1.0f - y - RAD) - 0.5f;
    float hiy = 64.0f * (1.0f - y + RAD) - 0.5f;

    if (!(hix >= 0.0f) || !(lox <= (float)(WW - 1))) return;
    if (!(hiy >= 0.0f) || !(loy <= (float)(HH - 1))) return;

    int ix0 = max(0, (int)floorf(fmaxf(lox, 0.0f)));
    int ix1 = min(WW - 1, (int)ceilf(fminf(hix, (float)(WW - 1))));
    int iy0 = max(0, (int)floorf(fmaxf(loy, 0.0f)));
    int iy1 = min(HH - 1, (int)ceilf(fminf(hiy, (float)(HH - 1))));
    if (ix0 > ix1 || iy0 > iy1) return;

    int tx0 = ix0 >> 4, tx1 = ix1 >> 4;
    int ty0 = iy0 >> 4, ty1 = iy1 >> 4;

    for (int ty = ty0; ty <= ty1; ty++) {
        for (int tx = tx0; tx <= tx1; tx++) {
            int tile = b * NTILES + ty * TX + tx;
            int pos = atomicAdd(&g_cnt[tile], 1);
            g_list[tile * NP + pos] = p;
        }
    }
}

// ---------------------------------------------------------------------------
// Kernel 2: per-tile raster. 256 threads = 16x16 pixels. Top-8 by z in regs.
// ---------------------------------------------------------------------------
__global__ void __launch_bounds__(256) raster_kernel(float* __restrict__ out) {
    int tx = blockIdx.x, ty = blockIdx.y, b = blockIdx.z;
    int tid = threadIdx.x;
    int lx = tid & 15, ly = tid >> 4;
    int px = tx * TILE + lx;
    int py = ty * TILE + ly;

    float gx = 1.0f - (px + 0.5f) * (1.0f / 64.0f);
    float gy = 1.0f - (py + 0.5f) * (1.0f / 64.0f);

    int tile = b * NTILES + ty * TX + tx;
    int n = g_cnt[tile];
    const int* __restrict__ list = g_list + tile * NP;
    const float* __restrict__ bpx = g_px + b * NP;
    const float* __restrict__ bpy = g_py + b * NP;
    const float* __restrict__ bpz = g_pz + b * NP;

    __shared__ float sx[256], sy[256], sz[256];
    __shared__ int   si[256];

    float zb[KK], db[KK];
    int   ib[KK];
#pragma unroll
    for (int k = 0; k < KK; k++) { zb[k] = ZINF; db[k] = -1.0f; ib[k] = -1; }

    for (int base = 0; base < n; base += 256) {
        int m = min(256, n - base);
        __syncthreads();
        if (tid < m) {
            int p = list[base + tid];
            si[tid] = p;
            sx[tid] = bpx[p];
            sy[tid] = bpy[p];
            sz[tid] = bpz[p];
        }
        __syncthreads();
        for (int j = 0; j < m; j++) {
            float dx = gx - sx[j];
            float dy = gy - sy[j];
            float d2 = dx * dx + dy * dy;
            float zc = sz[j];
            if (d2 < RAD2 && zc < zb[KK - 1]) {
                float zi = zc, di = d2;
                int ii = si[j];
#pragma unroll
                for (int k = 0; k < KK; k++) {
                    if (zi < zb[k]) {
                        float tz = zb[k]; zb[k] = zi; zi = tz;
                        float td = db[k]; db[k] = di; di = td;
                        int   ti = ib[k]; ib[k] = ii; ii = ti;
                    }
                }
            }
        }
    }

    const int N = BATCH * HH * WW * KK;
    int obase = ((b * HH + py) * WW + px) * KK;
#pragma unroll
    for (int k = 0; k < KK; k++) {
        bool v = zb[k] < ZINF;
        out[obase + k]         = v ? (float)ib[k] : -1.0f;  // idx
        out[N + obase + k]     = v ? zb[k]        : -1.0f;  // zbuf
        out[2 * N + obase + k] = v ? db[k]        : -1.0f;  // dists
    }
}

// ---------------------------------------------------------------------------
extern "C" void kernel_launch(void* const* d_in, const int* in_sizes, int n_in,
                              void* d_out, int out_size) {
    const float* pts = (const float*)d_in[0];
    const float* Rm  = (const float*)d_in[1];
    const float* Tv  = (const float*)d_in[2];
    const float* Fc  = (const float*)d_in[3];
    float* out = (float*)d_out;

    zero_counts_kernel<<<1, 128>>>();
    transform_bin_kernel<<<(BATCH * NP + 255) / 256, 256>>>(pts, Rm, Tv, Fc);
    raster_kernel<<<dim3(TX, TYN, BATCH), 256>>>(out);
}